// round 3
// baseline (speedup 1.0000x reference)
#include <cuda_runtime.h>

#define BS           24
#define C_REP        16
#define H_DIM        320
#define W_DIM        320
#define HW           (H_DIM * W_DIM)         // 102400
#define HW4          (HW / 4)                // 25600 float4 per channel row
#define N_PIX        (BS * HW)               // 2457600
#define N_VEC        (N_PIX / 4)             // 614400
#define NUM_CLASSES  4
#define NUM_MICRO    4
#define NSEG         (NUM_CLASSES * NUM_MICRO)
#define SEG_STRIDE   17
#define SCRATCH_N    (NSEG * SEG_STRIDE)     // 272
#define MOMENTUM     0.99f

#define GRID_DIM     1184
#define BLOCK_DIM    256

__device__ float g_scratch[SCRATCH_N];   // zero-init at load; reset each call
__device__ unsigned int g_ticket;        // zero-init; reset each call

__global__ __launch_bounds__(BLOCK_DIM) void fused_kernel(
    const float* __restrict__ rep,          // [BS, C_REP, H, W]
    const int* __restrict__ pmi,            // [BS, H, W, NUM_CLASSES]
    const int* __restrict__ target,         // [BS, H, W]
    const int* __restrict__ smask,          // [H, W]
    const unsigned char* __restrict__ cond, // [BS, H, W] bool
    const float* __restrict__ protos,       // [NSEG*C_REP]
    float* __restrict__ out                 // [NSEG*C_REP]
) {
    __shared__ float s_acc[SCRATCH_N];
    const int tid = threadIdx.x;
    for (int i = tid; i < SCRATCH_N; i += BLOCK_DIM)
        s_acc[i] = 0.0f;
    __syncthreads();

    const int4*   __restrict__ target4 = (const int4*)target;
    const uchar4* __restrict__ cond4   = (const uchar4*)cond;
    const int4*   __restrict__ smask4  = (const int4*)smask;

    const unsigned stride = GRID_DIM * BLOCK_DIM;
    for (unsigned v = blockIdx.x * BLOCK_DIM + tid; v < N_VEC; v += stride) {
        int4   t4 = target4[v];
        uchar4 c4 = cond4[v];
        unsigned n0  = 4u * v;
        unsigned b   = n0 / HW;
        unsigned hw4 = n0 % HW;            // multiple of 4
        int4 m4 = smask4[hw4 >> 2];

        int tgt[4] = {t4.x, t4.y, t4.z, t4.w};
        bool val[4];
        val[0] = (t4.x != 0) & (c4.x != 0) & (m4.x == 1);
        val[1] = (t4.y != 0) & (c4.y != 0) & (m4.y == 1);
        val[2] = (t4.z != 0) & (c4.z != 0) & (m4.z == 1);
        val[3] = (t4.w != 0) & (c4.w != 0) & (m4.w == 1);
        if (!(val[0] | val[1] | val[2] | val[3])) continue;

        int seg[4];
        #pragma unroll
        for (int k = 0; k < 4; k++) {
            if (val[k])
                seg[k] = tgt[k] * NUM_MICRO
                       + pmi[4u * (n0 + k) + (unsigned)tgt[k]];
        }

        // rep as float4: channel c at offset c*HW4 (16B-aligned: hw4 % 4 == 0)
        const float4* __restrict__ r4 =
            (const float4*)(rep + (size_t)b * (C_REP * HW)) + (hw4 >> 2);

        // ---- channels 0..7: front-batched LDG.128 x8, then atomics ----
        {
            float4 vv[8];
            #pragma unroll
            for (int c = 0; c < 8; c++)
                vv[c] = r4[(size_t)c * HW4];
            #pragma unroll
            for (int k = 0; k < 4; k++) {
                if (val[k]) {
                    float* base = &s_acc[seg[k] * SEG_STRIDE];
                    #pragma unroll
                    for (int c = 0; c < 8; c++) {
                        const float* f = (const float*)&vv[c];
                        atomicAdd(&base[c], f[k]);
                    }
                }
            }
        }
        // ---- channels 8..15 ----
        {
            float4 vv[8];
            #pragma unroll
            for (int c = 0; c < 8; c++)
                vv[c] = r4[(size_t)(c + 8) * HW4];
            #pragma unroll
            for (int k = 0; k < 4; k++) {
                if (val[k]) {
                    float* base = &s_acc[seg[k] * SEG_STRIDE];
                    #pragma unroll
                    for (int c = 0; c < 8; c++) {
                        const float* f = (const float*)&vv[c];
                        atomicAdd(&base[c + 8], f[k]);
                    }
                }
            }
        }
        // ---- counts ----
        #pragma unroll
        for (int k = 0; k < 4; k++)
            if (val[k])
                atomicAdd(&s_acc[seg[k] * SEG_STRIDE + C_REP], 1.0f);
    }
    __syncthreads();

    // Flush per-CTA partials
    for (int i = tid; i < SCRATCH_N; i += BLOCK_DIM) {
        float valf = s_acc[i];
        if (valf != 0.0f) atomicAdd(&g_scratch[i], valf);
    }

    // Last CTA finalizes + resets state for the next graph replay
    __shared__ bool s_last;
    __threadfence();
    if (tid == 0) {
        unsigned t = atomicAdd(&g_ticket, 1u);
        s_last = (t == GRID_DIM - 1);
    }
    __syncthreads();
    if (!s_last) return;

    if (tid < NSEG * C_REP) {
        int seg = tid >> 4;
        int c = tid & 15;
        float cnt = __ldcg(&g_scratch[seg * SEG_STRIDE + C_REP]);
        float sum = __ldcg(&g_scratch[seg * SEG_STRIDE + c]);
        float mean = sum / fmaxf(cnt, 1.0f);
        float p = protos[tid];
        out[tid] = (cnt > 0.0f) ? (MOMENTUM * p + (1.0f - MOMENTUM) * mean) : p;
    }
    __syncthreads();

    for (int i = tid; i < SCRATCH_N; i += BLOCK_DIM)
        g_scratch[i] = 0.0f;
    if (tid == 0) g_ticket = 0u;
}

extern "C" void kernel_launch(void* const* d_in, const int* in_sizes, int n_in,
                              void* d_out, int out_size) {
    const float* rep           = (const float*)d_in[0];
    const int* pmi             = (const int*)d_in[1];
    const int* target          = (const int*)d_in[2];
    const int* smask           = (const int*)d_in[3];
    const unsigned char* cond  = (const unsigned char*)d_in[4];
    const float* protos        = (const float*)d_in[5];
    float* out                 = (float*)d_out;

    fused_kernel<<<GRID_DIM, BLOCK_DIM>>>(rep, pmi, target, smask, cond,
                                          protos, out);
}